// round 5
// baseline (speedup 1.0000x reference)
#include <cuda_runtime.h>
#include <cstdint>
#include <cstddef>

#define TOKS 4096
#define EMB  1024
#define HID  4096
#define NE   8
#define CAP  4096   // per-expert capacity (<= TOKS, each token picks an expert at most once)

// ---------------- scratch (device globals; no allocations allowed) ----------------
__device__ int   g_cnt[NE];
__device__ float g_sumprob[NE];
__device__ int   g_tok[NE * CAP];
__device__ int   g_map[TOKS * 2];     // token -> global slot (e*CAP + s)
__device__ float g_gatew[TOKS * 2];   // token -> gate weight
__device__ float g_xa[(size_t)NE * CAP * EMB];   // gathered activations   (128 MB)
__device__ float g_s1[(size_t)NE * CAP * HID];   // X@W1^T, then h (in-place) (512 MB)
__device__ float g_s2[(size_t)NE * CAP * HID];   // X@W2^T                 (512 MB)
__device__ float g_y [(size_t)NE * CAP * EMB];   // H@W3^T                 (128 MB)

// ---------------- helpers ----------------
__device__ __forceinline__ uint32_t f2tf(float f) {
    uint32_t u;
    asm("cvt.rna.tf32.f32 %0, %1;" : "=r"(u) : "f"(f));
    return u;
}

__device__ __forceinline__ void cpa16(void* s, const void* g) {
    uint32_t sa = (uint32_t)__cvta_generic_to_shared(s);
    asm volatile("cp.async.cg.shared.global [%0], [%1], 16;\n" :: "r"(sa), "l"(g));
}

__device__ __forceinline__ void mma_tf32(float* c, const uint32_t* a, const uint32_t* b) {
    asm volatile(
        "mma.sync.aligned.m16n8k8.row.col.f32.tf32.tf32.f32 "
        "{%0,%1,%2,%3}, {%4,%5,%6,%7}, {%8,%9}, {%0,%1,%2,%3};\n"
        : "+f"(c[0]), "+f"(c[1]), "+f"(c[2]), "+f"(c[3])
        : "r"(a[0]), "r"(a[1]), "r"(a[2]), "r"(a[3]), "r"(b[0]), "r"(b[1]));
}

// ---------------- kernels ----------------
__global__ void init_kernel() {
    int i = threadIdx.x;
    if (i < NE) { g_cnt[i] = 0; g_sumprob[i] = 0.f; }
}

// one warp per token: scores, top-2, softmax gates, slot assignment, aux accumulation
__global__ void router_kernel(const float* __restrict__ x, const float* __restrict__ gw) {
    __shared__ float s_ps[NE];
    int tid = threadIdx.x, lane = tid & 31, wid = tid >> 5;
    if (tid < NE) s_ps[tid] = 0.f;
    __syncthreads();

    int t = blockIdx.x * 8 + wid;
    float acc[NE];
#pragma unroll
    for (int e = 0; e < NE; e++) acc[e] = 0.f;
    const float* xr = x + (size_t)t * EMB;
    for (int i = lane; i < EMB; i += 32) {
        float xi = xr[i];
#pragma unroll
        for (int e = 0; e < NE; e++) acc[e] += xi * gw[e * EMB + i];
    }
#pragma unroll
    for (int e = 0; e < NE; e++) {
#pragma unroll
        for (int o = 16; o > 0; o >>= 1) acc[e] += __shfl_xor_sync(0xffffffffu, acc[e], o);
    }
    if (lane == 0) {
        // full softmax over 8 (aux loss)
        float m = acc[0];
#pragma unroll
        for (int e = 1; e < NE; e++) m = fmaxf(m, acc[e]);
        float pe[NE], se = 0.f;
#pragma unroll
        for (int e = 0; e < NE; e++) { pe[e] = expf(acc[e] - m); se += pe[e]; }
        float inv = 1.f / se;
#pragma unroll
        for (int e = 0; e < NE; e++) atomicAdd(&s_ps[e], pe[e] * inv);

        // top-2 (ties: lowest index first, matching jax top_k)
        int i1 = 0;
#pragma unroll
        for (int e = 1; e < NE; e++) if (acc[e] > acc[i1]) i1 = e;
        int i2 = (i1 == 0) ? 1 : 0;
#pragma unroll
        for (int e = 0; e < NE; e++) if (e != i1 && acc[e] > acc[i2]) i2 = e;

        float p1 = 1.f / (1.f + expf(acc[i2] - acc[i1]));
        float p2 = 1.f - p1;
        int s1 = atomicAdd(&g_cnt[i1], 1);
        int s2 = atomicAdd(&g_cnt[i2], 1);
        g_tok[i1 * CAP + s1] = t;
        g_tok[i2 * CAP + s2] = t;
        g_map[t * 2 + 0] = i1 * CAP + s1;
        g_map[t * 2 + 1] = i2 * CAP + s2;
        g_gatew[t * 2 + 0] = p1;
        g_gatew[t * 2 + 1] = p2;
    }
    __syncthreads();
    if (tid < NE) atomicAdd(&g_sumprob[tid], s_ps[tid]);
}

// one warp per (expert, slot): copy token row into expert-contiguous scratch
__global__ void gather_kernel(const float* __restrict__ x) {
    int w = (blockIdx.x * blockDim.x + threadIdx.x) >> 5;
    int lane = threadIdx.x & 31;
    int e = w >> 12, s = w & (CAP - 1);
    if (s >= g_cnt[e]) return;
    int t = g_tok[w];
    const float4* src = (const float4*)(x + (size_t)t * EMB);
    float4* dst = (float4*)(g_xa + (size_t)w * EMB);
#pragma unroll 4
    for (int i = lane; i < EMB / 4; i += 32) dst[i] = src[i];
}

// Grouped GEMM: C[m][n] = sum_k A[m][k] * W[n][k]  (tf32 mma.sync, 128x128x32 tiles)
// MODE 0: A=g_xa (K=EMB) , C=g_s1, N=HID   (W = w1)
// MODE 1: A=g_xa (K=EMB) , C=g_s2, N=HID   (W = w2)
// MODE 2: A=g_s1 (K=HID) , C=g_y , N=EMB   (W = w3)
template <int MODE>
__global__ __launch_bounds__(256, 2) void gemm_kernel(const float* __restrict__ W) {
    constexpr int K = (MODE == 2) ? HID : EMB;
    constexpr int N = (MODE == 2) ? EMB : HID;
    constexpr int LDS = 36;  // padded stride: conflict-free frag loads, 16B-aligned rows

    int e = blockIdx.z;
    int cnt = g_cnt[e];
    int mt = blockIdx.y;
    if (mt * 128 >= cnt) return;

    const float* A = (MODE == 2) ? g_s1 : g_xa;
    float* C = (MODE == 0) ? g_s1 : (MODE == 1) ? g_s2 : g_y;

    const float* Ae = A + (size_t)e * CAP * K + (size_t)mt * 128 * K;
    const float* Be = W + (size_t)e * N * K + (size_t)blockIdx.x * 128 * K;
    float* Ce = C + (size_t)e * CAP * N + (size_t)mt * 128 * N + blockIdx.x * 128;

    extern __shared__ float smem[];
    float* As = smem;                 // [2][128][LDS]
    float* Bs = smem + 2 * 128 * LDS; // [2][128][LDS]

    int tid = threadIdx.x, lane = tid & 31, wid = tid >> 5;
    int wm = wid & 1, wn = wid >> 1;  // warps: 2 x 4 -> warp tile 64(M) x 32(N)

    float acc[4][4][4];
#pragma unroll
    for (int m = 0; m < 4; m++)
#pragma unroll
        for (int n = 0; n < 4; n++)
#pragma unroll
            for (int i = 0; i < 4; i++) acc[m][n][i] = 0.f;

    const int NK = K / 32;

    auto load_stage = [&](int buf, int k0) {
        float* Ab = As + buf * 128 * LDS;
        float* Bb = Bs + buf * 128 * LDS;
#pragma unroll
        for (int i = 0; i < 4; i++) {
            int chunk = tid + i * 256;
            int r = chunk >> 3, c4 = (chunk & 7) * 4;
            cpa16(&Ab[r * LDS + c4], Ae + (size_t)r * K + k0 + c4);
            cpa16(&Bb[r * LDS + c4], Be + (size_t)r * K + k0 + c4);
        }
        asm volatile("cp.async.commit_group;\n");
    };

    load_stage(0, 0);

    for (int kt = 0; kt < NK; kt++) {
        asm volatile("cp.async.wait_group 0;\n");
        __syncthreads();
        if (kt + 1 < NK) load_stage((kt + 1) & 1, (kt + 1) * 32);

        const float* Asb = As + (kt & 1) * 128 * LDS;
        const float* Bsb = Bs + (kt & 1) * 128 * LDS;
#pragma unroll
        for (int ks = 0; ks < 4; ks++) {
            uint32_t af[4][4], bf[4][2];
            int kc = ks * 8 + (lane & 3);
#pragma unroll
            for (int m = 0; m < 4; m++) {
                int r = wm * 64 + m * 16 + (lane >> 2);
                af[m][0] = f2tf(Asb[r * LDS + kc]);
                af[m][1] = f2tf(Asb[(r + 8) * LDS + kc]);
                af[m][2] = f2tf(Asb[r * LDS + kc + 4]);
                af[m][3] = f2tf(Asb[(r + 8) * LDS + kc + 4]);
            }
#pragma unroll
            for (int n = 0; n < 4; n++) {
                int cn = wn * 32 + n * 8 + (lane >> 2);
                bf[n][0] = f2tf(Bsb[cn * LDS + kc]);
                bf[n][1] = f2tf(Bsb[cn * LDS + kc + 4]);
            }
#pragma unroll
            for (int m = 0; m < 4; m++)
#pragma unroll
                for (int n = 0; n < 4; n++) mma_tf32(acc[m][n], af[m], bf[n]);
        }
    }

    // epilogue: raw fp32 C (bias/activation handled elsewhere)
#pragma unroll
    for (int m = 0; m < 4; m++) {
#pragma unroll
        for (int n = 0; n < 4; n++) {
            int r = wm * 64 + m * 16 + (lane >> 2);
            int cb = wn * 32 + n * 8 + (lane & 3) * 2;
            float2 v0 = make_float2(acc[m][n][0], acc[m][n][1]);
            float2 v1 = make_float2(acc[m][n][2], acc[m][n][3]);
            *(float2*)(Ce + (size_t)r * N + cb) = v0;
            *(float2*)(Ce + (size_t)(r + 8) * N + cb) = v1;
        }
    }
}

// h = silu(s1 + b1) * (s2 + b2), in-place into g_s1
__global__ void act_kernel(const float* __restrict__ b1, const float* __restrict__ b2) {
    int w = (blockIdx.x * blockDim.x + threadIdx.x) >> 5;
    int lane = threadIdx.x & 31;
    int e = w >> 12, s = w & (CAP - 1);
    if (s >= g_cnt[e]) return;
    float4* r1 = (float4*)(g_s1 + (size_t)w * HID);
    const float4* r2 = (const float4*)(g_s2 + (size_t)w * HID);
    const float4* bb1 = (const float4*)(b1 + (size_t)e * HID);
    const float4* bb2 = (const float4*)(b2 + (size_t)e * HID);
    for (int i = lane; i < HID / 4; i += 32) {
        float4 a = r1[i], b = r2[i], c = bb1[i], d = bb2[i];
        float ax = a.x + c.x, ay = a.y + c.y, az = a.z + c.z, aw = a.w + c.w;
        float bx = b.x + d.x, by = b.y + d.y, bz = b.z + d.z, bw = b.w + d.w;
        float4 h;
        h.x = (ax / (1.f + expf(-ax))) * bx;
        h.y = (ay / (1.f + expf(-ay))) * by;
        h.z = (az / (1.f + expf(-az))) * bz;
        h.w = (aw / (1.f + expf(-aw))) * bw;
        r1[i] = h;
    }
}

// out[t] = sum_k gate_k * (Y[slot_k] + b3[e_k])   (one warp per token; fully writes d_out)
__global__ void combine_kernel(float* __restrict__ out, const float* __restrict__ b3) {
    int w = (blockIdx.x * blockDim.x + threadIdx.x) >> 5;
    int lane = threadIdx.x & 31;
    if (w >= TOKS) return;
    int m0 = g_map[2 * w], m1 = g_map[2 * w + 1];
    float p0 = g_gatew[2 * w], p1 = g_gatew[2 * w + 1];
    int e0 = m0 >> 12, e1 = m1 >> 12;
    const float4* y0 = (const float4*)(g_y + (size_t)m0 * EMB);
    const float4* y1 = (const float4*)(g_y + (size_t)m1 * EMB);
    const float4* bb0 = (const float4*)(b3 + (size_t)e0 * EMB);
    const float4* bb1 = (const float4*)(b3 + (size_t)e1 * EMB);
    float4* o = (float4*)(out + (size_t)w * EMB);
    for (int i = lane; i < EMB / 4; i += 32) {
        float4 a = y0[i], b = y1[i], c = bb0[i], d = bb1[i];
        float4 r;
        r.x = p0 * (a.x + c.x) + p1 * (b.x + d.x);
        r.y = p0 * (a.y + c.y) + p1 * (b.y + d.y);
        r.z = p0 * (a.z + c.z) + p1 * (b.z + d.z);
        r.w = p0 * (a.w + c.w) + p1 * (b.w + d.w);
        o[i] = r;
    }
}

__global__ void aux_kernel(float* __restrict__ out, int out_size) {
    if (threadIdx.x == 0 && blockIdx.x == 0 && out_size > TOKS * EMB) {
        float a = 0.f;
        for (int e = 0; e < NE; e++)
            a += ((float)g_cnt[e] / (float)TOKS) * (g_sumprob[e] / (float)TOKS);
        out[TOKS * EMB] = (float)NE * a;
    }
}

// ---------------- launcher ----------------
extern "C" void kernel_launch(void* const* d_in, const int* in_sizes, int n_in,
                              void* d_out, int out_size) {
    const float* x  = (const float*)d_in[0];
    const float* gw = (const float*)d_in[1];
    const float* w1 = (const float*)d_in[2];
    const float* b1 = (const float*)d_in[3];
    const float* w2 = (const float*)d_in[4];
    const float* b2 = (const float*)d_in[5];
    const float* w3 = (const float*)d_in[6];
    const float* b3 = (const float*)d_in[7];
    float* out = (float*)d_out;

    const int SMEM_BYTES = 2 * 2 * 128 * 36 * 4;  // 73728

    cudaFuncSetAttribute(gemm_kernel<0>, cudaFuncAttributeMaxDynamicSharedMemorySize, SMEM_BYTES);
    cudaFuncSetAttribute(gemm_kernel<1>, cudaFuncAttributeMaxDynamicSharedMemorySize, SMEM_BYTES);
    cudaFuncSetAttribute(gemm_kernel<2>, cudaFuncAttributeMaxDynamicSharedMemorySize, SMEM_BYTES);

    init_kernel<<<1, 32>>>();
    router_kernel<<<TOKS / 8, 256>>>(x, gw);
    gather_kernel<<<NE * CAP / 8, 256>>>(x);
    gemm_kernel<0><<<dim3(HID / 128, CAP / 128, NE), 256, SMEM_BYTES>>>(w1);
    gemm_kernel<1><<<dim3(HID / 128, CAP / 128, NE), 256, SMEM_BYTES>>>(w2);
    act_kernel<<<NE * CAP / 8, 256>>>(b1, b2);
    gemm_kernel<2><<<dim3(EMB / 128, CAP / 128, NE), 256, SMEM_BYTES>>>(w3);
    combine_kernel<<<TOKS / 8, 256>>>(out, b3);
    aux_kernel<<<1, 32>>>(out, out_size);
}

// round 7
// speedup vs baseline: 1.1282x; 1.1282x over previous
#include <cuda_runtime.h>
#include <cstdint>
#include <cstddef>

#define TOKS 4096
#define EMB  1024
#define HID  4096
#define NE   8
#define CAP  4096   // per-expert capacity

// ---------------- scratch (device globals; no allocations allowed) ----------------
__device__ int   g_cnt[NE];
__device__ float g_sumprob[NE];
__device__ int   g_tok[NE * CAP];
__device__ int   g_map[TOKS * 2];     // token -> global slot (e*CAP + s)
__device__ float g_gatew[TOKS * 2];   // token -> gate weight
__device__ float g_xa[(size_t)NE * CAP * EMB];   // gathered activations, tf32 bits (128 MB)
__device__ float g_s1[(size_t)NE * CAP * HID];   // X@W1^T (fp32), then h (tf32 bits, in-place)
__device__ float g_s2[(size_t)NE * CAP * HID];   // X@W2^T (fp32)
__device__ float g_y [(size_t)NE * CAP * EMB];   // H@W3^T (fp32)

// ---------------- helpers ----------------
__device__ __forceinline__ uint32_t f2tf(float f) {
    uint32_t u;
    asm("cvt.rna.tf32.f32 %0, %1;" : "=r"(u) : "f"(f));
    return u;
}

__device__ __forceinline__ void cpa16(void* s, const void* g) {
    uint32_t sa = (uint32_t)__cvta_generic_to_shared(s);
    asm volatile("cp.async.cg.shared.global [%0], [%1], 16;\n" :: "r"(sa), "l"(g));
}

__device__ __forceinline__ void mma_tf32(float* c, const uint32_t* a, const uint32_t* b) {
    asm volatile(
        "mma.sync.aligned.m16n8k8.row.col.f32.tf32.tf32.f32 "
        "{%0,%1,%2,%3}, {%4,%5,%6,%7}, {%8,%9}, {%0,%1,%2,%3};\n"
        : "+f"(c[0]), "+f"(c[1]), "+f"(c[2]), "+f"(c[3])
        : "r"(a[0]), "r"(a[1]), "r"(a[2]), "r"(a[3]), "r"(b[0]), "r"(b[1]));
}

__device__ __forceinline__ float silu_mul(float a, float b) {
    return (a / (1.f + expf(-a))) * b;
}

// ---------------- kernels ----------------
__global__ void init_kernel() {
    int i = threadIdx.x;
    if (i < NE) { g_cnt[i] = 0; g_sumprob[i] = 0.f; }
}

// one warp per token: scores, top-2, softmax gates, slot assignment, aux accumulation
__global__ void router_kernel(const float* __restrict__ x, const float* __restrict__ gw) {
    __shared__ float s_ps[NE];
    int tid = threadIdx.x, lane = tid & 31, wid = tid >> 5;
    if (tid < NE) s_ps[tid] = 0.f;
    __syncthreads();

    int t = blockIdx.x * 8 + wid;
    float acc[NE];
#pragma unroll
    for (int e = 0; e < NE; e++) acc[e] = 0.f;
    const float* xr = x + (size_t)t * EMB;
    for (int i = lane; i < EMB; i += 32) {
        float xi = xr[i];
#pragma unroll
        for (int e = 0; e < NE; e++) acc[e] += xi * gw[e * EMB + i];
    }
#pragma unroll
    for (int e = 0; e < NE; e++) {
#pragma unroll
        for (int o = 16; o > 0; o >>= 1) acc[e] += __shfl_xor_sync(0xffffffffu, acc[e], o);
    }
    if (lane == 0) {
        float m = acc[0];
#pragma unroll
        for (int e = 1; e < NE; e++) m = fmaxf(m, acc[e]);
        float pe[NE], se = 0.f;
#pragma unroll
        for (int e = 0; e < NE; e++) { pe[e] = expf(acc[e] - m); se += pe[e]; }
        float inv = 1.f / se;
#pragma unroll
        for (int e = 0; e < NE; e++) atomicAdd(&s_ps[e], pe[e] * inv);

        // top-2 (ties: lowest index first, matching jax top_k)
        int i1 = 0;
#pragma unroll
        for (int e = 1; e < NE; e++) if (acc[e] > acc[i1]) i1 = e;
        int i2 = (i1 == 0) ? 1 : 0;
#pragma unroll
        for (int e = 0; e < NE; e++) if (e != i1 && acc[e] > acc[i2]) i2 = e;

        float p1 = 1.f / (1.f + expf(acc[i2] - acc[i1]));
        float p2 = 1.f - p1;
        int s1 = atomicAdd(&g_cnt[i1], 1);
        int s2 = atomicAdd(&g_cnt[i2], 1);
        g_tok[i1 * CAP + s1] = t;
        g_tok[i2 * CAP + s2] = t;
        g_map[t * 2 + 0] = i1 * CAP + s1;
        g_map[t * 2 + 1] = i2 * CAP + s2;
        g_gatew[t * 2 + 0] = p1;
        g_gatew[t * 2 + 1] = p2;
    }
    __syncthreads();
    if (tid < NE) atomicAdd(&g_sumprob[tid], s_ps[tid]);
}

// one warp per (expert, slot): copy token row into expert-contiguous scratch,
// converting to tf32 so the GEMM A-fragment loads need no cvt.
__global__ void gather_kernel(const float* __restrict__ x) {
    int w = (blockIdx.x * blockDim.x + threadIdx.x) >> 5;
    int lane = threadIdx.x & 31;
    int e = w >> 12, s = w & (CAP - 1);
    if (s >= g_cnt[e]) return;
    int t = g_tok[w];
    const float4* src = (const float4*)(x + (size_t)t * EMB);
    float4* dst = (float4*)(g_xa + (size_t)w * EMB);
#pragma unroll 4
    for (int i = lane; i < EMB / 4; i += 32) {
        float4 v = src[i];
        float4 o;
        o.x = __uint_as_float(f2tf(v.x));
        o.y = __uint_as_float(f2tf(v.y));
        o.z = __uint_as_float(f2tf(v.z));
        o.w = __uint_as_float(f2tf(v.w));
        dst[i] = o;
    }
}

// Grouped GEMM: C[m][n] = sum_k A[m][k] * W[n][k]  (tf32 mma.sync, 128x128x32 tiles)
// A operand is PRE-CONVERTED to tf32 bits (g_xa / g_s1-as-h); B (weights) cvt in-loop.
// MODE 0: A=g_xa (K=EMB), C=g_s1, N=HID   (W = w1) — raw fp32 epilogue
// MODE 1: A=g_xa (K=EMB), C=g_s2, N=HID   (W = w2) — FUSED epilogue:
//         h = silu(s1+b1)*(acc+b2) stored as tf32 bits in-place into g_s1
// MODE 2: A=g_s1 (K=HID), C=g_y , N=EMB   (W = w3) — raw fp32 epilogue
template <int MODE>
__global__ __launch_bounds__(256, 2) void gemm_kernel(const float* __restrict__ W,
                                                      const float* __restrict__ bias1,
                                                      const float* __restrict__ bias2) {
    constexpr int K = (MODE == 2) ? HID : EMB;
    constexpr int N = (MODE == 2) ? EMB : HID;
    constexpr int LDS = 36;  // padded stride

    int e = blockIdx.z;
    int cnt = g_cnt[e];
    int mt = blockIdx.y;
    if (mt * 128 >= cnt) return;

    const float* A = (MODE == 2) ? g_s1 : g_xa;
    float* C = (MODE == 0) ? g_s1 : (MODE == 1) ? g_s2 : g_y;

    const float* Ae = A + (size_t)e * CAP * K + (size_t)mt * 128 * K;
    const float* Be = W + (size_t)e * N * K + (size_t)blockIdx.x * 128 * K;
    float* Ce = C + (size_t)e * CAP * N + (size_t)mt * 128 * N + blockIdx.x * 128;

    extern __shared__ float smem[];
    float* As = smem;                 // [2][128][LDS]
    float* Bs = smem + 2 * 128 * LDS; // [2][128][LDS]

    int tid = threadIdx.x, lane = tid & 31, wid = tid >> 5;
    int wm = wid & 1, wn = wid >> 1;  // warps: 2 x 4 -> warp tile 64(M) x 32(N)

    float acc[4][4][4];
#pragma unroll
    for (int m = 0; m < 4; m++)
#pragma unroll
        for (int n = 0; n < 4; n++)
#pragma unroll
            for (int i = 0; i < 4; i++) acc[m][n][i] = 0.f;

    const int NK = K / 32;

    auto load_stage = [&](int buf, int k0) {
        float* Ab = As + buf * 128 * LDS;
        float* Bb = Bs + buf * 128 * LDS;
#pragma unroll
        for (int i = 0; i < 4; i++) {
            int chunk = tid + i * 256;
            int r = chunk >> 3, c4 = (chunk & 7) * 4;
            cpa16(&Ab[r * LDS + c4], Ae + (size_t)r * K + k0 + c4);
            cpa16(&Bb[r * LDS + c4], Be + (size_t)r * K + k0 + c4);
        }
        asm volatile("cp.async.commit_group;\n");
    };

    load_stage(0, 0);

    for (int kt = 0; kt < NK; kt++) {
        asm volatile("cp.async.wait_group 0;\n");
        __syncthreads();
        if (kt + 1 < NK) load_stage((kt + 1) & 1, (kt + 1) * 32);

        const float* Asb = As + (kt & 1) * 128 * LDS;
        const float* Bsb = Bs + (kt & 1) * 128 * LDS;
#pragma unroll
        for (int ks = 0; ks < 4; ks++) {
            uint32_t af[4][4], bf[4][2];
            int kc = ks * 8 + (lane & 3);
#pragma unroll
            for (int m = 0; m < 4; m++) {
                int r = wm * 64 + m * 16 + (lane >> 2);
                af[m][0] = __float_as_uint(Asb[r * LDS + kc]);          // pre-converted tf32
                af[m][1] = __float_as_uint(Asb[(r + 8) * LDS + kc]);
                af[m][2] = __float_as_uint(Asb[r * LDS + kc + 4]);
                af[m][3] = __float_as_uint(Asb[(r + 8) * LDS + kc + 4]);
            }
#pragma unroll
            for (int n = 0; n < 4; n++) {
                int cn = wn * 32 + n * 8 + (lane >> 2);
                bf[n][0] = f2tf(Bsb[cn * LDS + kc]);
                bf[n][1] = f2tf(Bsb[cn * LDS + kc + 4]);
            }
#pragma unroll
            for (int m = 0; m < 4; m++)
#pragma unroll
                for (int n = 0; n < 4; n++) mma_tf32(acc[m][n], af[m], bf[n]);
        }
    }

    if (MODE == 1) {
        // Fused activation epilogue: h = silu(s1+b1)*(s2+b2), stored as tf32 bits
        // in-place into g_s1 (consumed raw by gemm<2>). Also keep s2 store cheap: skip it.
        float* S1e = g_s1 + (size_t)e * CAP * N + (size_t)mt * 128 * N + blockIdx.x * 128;
        const float* b1p = bias1 + (size_t)e * HID + blockIdx.x * 128;
        const float* b2p = bias2 + (size_t)e * HID + blockIdx.x * 128;
#pragma unroll
        for (int n = 0; n < 4; n++) {
            int cb = wn * 32 + n * 8 + (lane & 3) * 2;
            float b1x = b1p[cb], b1y = b1p[cb + 1];
            float b2x = b2p[cb], b2y = b2p[cb + 1];
#pragma unroll
            for (int m = 0; m < 4; m++) {
                int r = wm * 64 + m * 16 + (lane >> 2);
                float2 s1a = *(const float2*)(S1e + (size_t)r * N + cb);
                float2 s1b = *(const float2*)(S1e + (size_t)(r + 8) * N + cb);
                float h0 = silu_mul(s1a.x + b1x, acc[m][n][0] + b2x);
                float h1 = silu_mul(s1a.y + b1y, acc[m][n][1] + b2y);
                float h2 = silu_mul(s1b.x + b1x, acc[m][n][2] + b2x);
                float h3 = silu_mul(s1b.y + b1y, acc[m][n][3] + b2y);
                float2 o0, o1;
                o0.x = __uint_as_float(f2tf(h0));
                o0.y = __uint_as_float(f2tf(h1));
                o1.x = __uint_as_float(f2tf(h2));
                o1.y = __uint_as_float(f2tf(h3));
                *(float2*)(S1e + (size_t)r * N + cb) = o0;
                *(float2*)(S1e + (size_t)(r + 8) * N + cb) = o1;
            }
        }
    } else {
        // raw fp32 epilogue
#pragma unroll
        for (int m = 0; m < 4; m++) {
#pragma unroll
            for (int n = 0; n < 4; n++) {
                int r = wm * 64 + m * 16 + (lane >> 2);
                int cb = wn * 32 + n * 8 + (lane & 3) * 2;
                float2 v0 = make_float2(acc[m][n][0], acc[m][n][1]);
                float2 v1 = make_float2(acc[m][n][2], acc[m][n][3]);
                *(float2*)(Ce + (size_t)r * N + cb) = v0;
                *(float2*)(Ce + (size_t)(r + 8) * N + cb) = v1;
            }
        }
    }
}

// out[t] = sum_k gate_k * (Y[slot_k] + b3[e_k])   (one warp per token; fully writes d_out)
__global__ void combine_kernel(float* __restrict__ out, const float* __restrict__ b3) {
    int w = (blockIdx.x * blockDim.x + threadIdx.x) >> 5;
    int lane = threadIdx.x & 31;
    if (w >= TOKS) return;
    int m0 = g_map[2 * w], m1 = g_map[2 * w + 1];
    float p0 = g_gatew[2 * w], p1 = g_gatew[2 * w + 1];
    int e0 = m0 >> 12, e1 = m1 >> 12;
    const float4* y0 = (const float4*)(g_y + (size_t)m0 * EMB);
    const float4* y1 = (const float4*)(g_y + (size_t)m1 * EMB);
    const float4* bb0 = (const float4*)(b3 + (size_t)e0 * EMB);
    const float4* bb1 = (const float4*)(b3 + (size_t)e1 * EMB);
    float4* o = (float4*)(out + (size_t)w * EMB);
    for (int i = lane; i < EMB / 4; i += 32) {
        float4 a = y0[i], b = y1[i], c = bb0[i], d = bb1[i];
        float4 r;
        r.x = p0 * (a.x + c.x) + p1 * (b.x + d.x);
        r.y = p0 * (a.y + c.y) + p1 * (b.y + d.y);
        r.z = p0 * (a.z + c.z) + p1 * (b.z + d.z);
        r.w = p0 * (a.w + c.w) + p1 * (b.w + d.w);
        o[i] = r;
    }
}

__global__ void aux_kernel(float* __restrict__ out, int out_size) {
    if (threadIdx.x == 0 && blockIdx.x == 0 && out_size > TOKS * EMB) {
        float a = 0.f;
        for (int e = 0; e < NE; e++)
            a += ((float)g_cnt[e] / (float)TOKS) * (g_sumprob[e] / (float)TOKS);
        out[TOKS * EMB] = (float)NE * a;
    }
}

// ---------------- launcher ----------------
extern "C" void kernel_launch(void* const* d_in, const int* in_sizes, int n_in,
                              void* d_out, int out_size) {
    const float* x  = (const float*)d_in[0];
    const float* gw = (const float*)d_in[1];
    const float* w1 = (const float*)d_in[2];
    const float* b1 = (const float*)d_in[3];
    const float* w2 = (const float*)d_in[4];
    const float* b2 = (const float*)d_in[5];
    const float* w3 = (const float*)d_in[6];
    const float* b3 = (const float*)d_in[7];
    float* out = (float*)d_out;

    const int SMEM_BYTES = 2 * 2 * 128 * 36 * 4;  // 73728

    cudaFuncSetAttribute(gemm_kernel<0>, cudaFuncAttributeMaxDynamicSharedMemorySize, SMEM_BYTES);
    cudaFuncSetAttribute(gemm_kernel<1>, cudaFuncAttributeMaxDynamicSharedMemorySize, SMEM_BYTES);
    cudaFuncSetAttribute(gemm_kernel<2>, cudaFuncAttributeMaxDynamicSharedMemorySize, SMEM_BYTES);

    init_kernel<<<1, 32>>>();
    router_kernel<<<TOKS / 8, 256>>>(x, gw);
    gather_kernel<<<NE * CAP / 8, 256>>>(x);
    gemm_kernel<0><<<dim3(HID / 128, CAP / 128, NE), 256, SMEM_BYTES>>>(w1, nullptr, nullptr);
    gemm_kernel<1><<<dim3(HID / 128, CAP / 128, NE), 256, SMEM_BYTES>>>(w2, b1, b2);
    gemm_kernel<2><<<dim3(EMB / 128, CAP / 128, NE), 256, SMEM_BYTES>>>(w3, nullptr, nullptr);
    combine_kernel<<<TOKS / 8, 256>>>(out, b3);
    aux_kernel<<<1, 32>>>(out, out_size);
}